// round 1
// baseline (speedup 1.0000x reference)
#include <cuda_runtime.h>
#include <cstdint>

// Problem constants
#define NF 8
#define NK 16
#define NY 16
#define NX 16
#define NP 32
#define NT 8
#define NB 64
#define VOL (NY*NX*NP*NT)   // 65536 elements per (b,f)
#define COLS (NY*NX*NP)     // 8192 (y,x,p) points per (b,f)

// Small precomputed tables (device globals — no allocation allowed)
__device__ float g_klat[NF*NK*NY];
__device__ float g_klon[NF*NK*NX];
__device__ float g_klev[NF*NK*NP];
__device__ float g_r[NF*NK];      // geometric ratio exp(-1/tau)
__device__ float g_rinv[NF*NK];   // 1 / (integrated + 1e-4)

using u64 = unsigned long long;

// Packed f32x2 helpers (B300 packed fp32 pipe: 2x FFMA throughput)
__device__ __forceinline__ u64 pk2(float lo, float hi) {
    u64 r; asm("mov.b64 %0,{%1,%2};" : "=l"(r) : "f"(lo), "f"(hi)); return r;
}
__device__ __forceinline__ u64 fma2(u64 a, u64 b, u64 c) {
    u64 d; asm("fma.rn.f32x2 %0,%1,%2,%3;" : "=l"(d) : "l"(a), "l"(b), "l"(c)); return d;
}
__device__ __forceinline__ u64 mul2(u64 a, u64 b) {
    u64 d; asm("mul.rn.f32x2 %0,%1,%2;" : "=l"(d) : "l"(a), "l"(b)); return d;
}
__device__ __forceinline__ float2 up2(u64 a) {
    float2 v; asm("mov.b64 {%0,%1},%2;" : "=f"(v.x), "=f"(v.y) : "l"(a)); return v;
}

// ---------------------------------------------------------------------------
// Prep kernel: one CTA per (f,k). Builds 1D kernel tables, the geometric
// time ratio r, and integrated[f,k] = sum(kernelparams * qw) + 1e-4.
// ---------------------------------------------------------------------------
__global__ void prep_kernel(const float* __restrict__ qw,
                            const float* __restrict__ mu_lat, const float* __restrict__ ls_lat,
                            const float* __restrict__ mu_lon, const float* __restrict__ ls_lon,
                            const float* __restrict__ mu_lev, const float* __restrict__ ls_lev,
                            const float* __restrict__ lt_time)
{
    const int fk = blockIdx.x;    // f*NK + k
    const int tid = threadIdx.x;
    __shared__ float s_lat[NY], s_lon[NX], s_lev[NP], s_t[NT];
    __shared__ float s_part[8];

    if (tid < NY) {
        float c = -1.f + 2.f * (float)tid / (float)(NY - 1);
        float z = (c - mu_lat[fk]) / expf(ls_lat[fk]);
        float v = expf(-0.5f * z * z);
        s_lat[tid] = v; g_klat[fk*NY + tid] = v;
    } else if (tid < 32) {
        int x = tid - 16;
        float c = -1.f + 2.f * (float)x / (float)(NX - 1);
        float z = (c - mu_lon[fk]) / expf(ls_lon[fk]);
        float v = expf(-0.5f * z * z);
        s_lon[x] = v; g_klon[fk*NX + x] = v;
    } else if (tid < 64) {
        int p = tid - 32;
        float c = -1.f + 2.f * (float)p / (float)(NP - 1);
        float z = (c - mu_lev[fk]) / expf(ls_lev[fk]);
        float v = expf(-0.5f * z * z);
        s_lev[p] = v; g_klev[fk*NP + p] = v;
    } else if (tid < 64 + NT) {
        int t = tid - 64;
        float tau = expf(lt_time[fk]) + 1e-6f;
        s_t[t] = expf(-(float)t / tau);
        if (t == 0) g_r[fk] = expf(-1.f / tau);
    }
    __syncthreads();

    // integrated = sum over all 65536 points of separable product * qw
    float local = 0.f;
    for (int idx = tid; idx < VOL; idx += blockDim.x) {
        int t = idx & 7;
        int p = (idx >> 3) & 31;
        int x = (idx >> 8) & 15;
        int y = idx >> 12;
        local += s_lat[y] * s_lon[x] * s_lev[p] * s_t[t] * qw[idx];
    }
    #pragma unroll
    for (int o = 16; o; o >>= 1) local += __shfl_xor_sync(0xffffffffu, local, o);
    if ((tid & 31) == 0) s_part[tid >> 5] = local;
    __syncthreads();
    if (tid == 0) {
        float s = 0.f;
        #pragma unroll
        for (int w = 0; w < 8; ++w) s += s_part[w];
        g_rinv[fk] = 1.f / (s + 1e-4f);
    }
}

// ---------------------------------------------------------------------------
// Main kernel: one CTA per (b,f) pair (512 CTAs, 256 threads).
// Thread layout: idx = j*256 + tid over the 8192 (y,x,p) points.
//   p = tid & 31 is CONSTANT per thread -> klev applied once at the end.
//   (y,x) uniform per warp per iteration -> clatlon LDS is broadcast.
// Inner math: per point, packed Horner over t (ktime is geometric) for
// 8 k-pairs, then one packed FMA with clatlon.
// ---------------------------------------------------------------------------
__global__ __launch_bounds__(256)
void feat_kernel(const float* __restrict__ patch,
                 const float* __restrict__ qw,
                 float* __restrict__ out)
{
    const int bf = blockIdx.x;        // b*NF + f
    const int f  = bf & (NF - 1);
    const int tid = threadIdx.x;

    __shared__ __align__(16) float s_cl[NY*NX*NK];   // clatlon[yx][k], 16 KB
    __shared__ float s_red[8*NK];

    // Build combined lat*lon table for this f
    for (int i = tid; i < NY*NX*NK; i += 256) {
        int k  = i & 15;
        int yx = i >> 4;
        int x  = yx & 15;
        int y  = yx >> 4;
        s_cl[i] = g_klat[(f*NK + k)*NY + y] * g_klon[(f*NK + k)*NX + x];
    }

    const int p = tid & 31;           // fixed plev per thread
    u64 r2[8], kv2[8], acc[8];
    #pragma unroll
    for (int kp = 0; kp < 8; ++kp) {
        int k0 = f*NK + 2*kp;
        r2[kp]  = pk2(g_r[k0], g_r[k0+1]);
        kv2[kp] = pk2(g_klev[k0*NP + p], g_klev[(k0+1)*NP + p]);
        acc[kp] = 0ull;               // (0.f, 0.f)
    }
    __syncthreads();

    const float4* pbase = (const float4*)(patch + (size_t)bf * VOL);
    const float4* qbase = (const float4*)qw;

    for (int j = 0; j < COLS/256; ++j) {
        const int idx = j*256 + tid;
        float4 a0 = pbase[idx*2];
        float4 a1 = pbase[idx*2 + 1];
        float4 q0 = qbase[idx*2];
        float4 q1 = qbase[idx*2 + 1];

        float wp0 = a0.x*q0.x, wp1 = a0.y*q0.y, wp2 = a0.z*q0.z, wp3 = a0.w*q0.w;
        float wp4 = a1.x*q1.x, wp5 = a1.y*q1.y, wp6 = a1.z*q1.z, wp7 = a1.w*q1.w;
        u64 w[8];
        w[0] = pk2(wp0, wp0); w[1] = pk2(wp1, wp1);
        w[2] = pk2(wp2, wp2); w[3] = pk2(wp3, wp3);
        w[4] = pk2(wp4, wp4); w[5] = pk2(wp5, wp5);
        w[6] = pk2(wp6, wp6); w[7] = pk2(wp7, wp7);

        const u64* cl = (const u64*)(s_cl + (idx >> 5) * NK);  // warp-uniform

        #pragma unroll
        for (int kp = 0; kp < 8; ++kp) {
            // Horner: s = ((wp7*r + wp6)*r + wp5)... = sum_t wp[t] * r^t
            u64 s = w[7];
            #pragma unroll
            for (int t = 6; t >= 0; --t) s = fma2(s, r2[kp], w[t]);
            acc[kp] = fma2(s, cl[kp], acc[kp]);
        }
    }

    // Apply klev (per-thread constant), unpack, block-reduce 256 -> 1 per k
    float v[16];
    #pragma unroll
    for (int kp = 0; kp < 8; ++kp) {
        float2 t2 = up2(mul2(acc[kp], kv2[kp]));
        v[2*kp]   = t2.x;
        v[2*kp+1] = t2.y;
    }
    #pragma unroll
    for (int kk = 0; kk < 16; ++kk) {
        #pragma unroll
        for (int o = 16; o; o >>= 1) v[kk] += __shfl_xor_sync(0xffffffffu, v[kk], o);
    }
    const int lane = tid & 31, wrp = tid >> 5;
    if (lane == 0) {
        #pragma unroll
        for (int kk = 0; kk < 16; ++kk) s_red[wrp*NK + kk] = v[kk];
    }
    __syncthreads();
    if (tid < NK) {
        float s = 0.f;
        #pragma unroll
        for (int w8 = 0; w8 < 8; ++w8) s += s_red[w8*NK + tid];
        // out[b][f*NK + k]
        out[(size_t)(bf >> 3) * (NF*NK) + f*NK + tid] = s * g_rinv[f*NK + tid];
    }
}

// ---------------------------------------------------------------------------
// Launch. Inputs (metadata order): patch, quadweights, mu_lat, logsigma_lat,
// mu_lon, logsigma_lon, mu_lev, logsigma_lev, logtau_time.
// ---------------------------------------------------------------------------
extern "C" void kernel_launch(void* const* d_in, const int* in_sizes, int n_in,
                              void* d_out, int out_size)
{
    (void)in_sizes; (void)n_in; (void)out_size;
    const float* patch  = (const float*)d_in[0];
    const float* qw     = (const float*)d_in[1];
    const float* mu_lat = (const float*)d_in[2];
    const float* ls_lat = (const float*)d_in[3];
    const float* mu_lon = (const float*)d_in[4];
    const float* ls_lon = (const float*)d_in[5];
    const float* mu_lev = (const float*)d_in[6];
    const float* ls_lev = (const float*)d_in[7];
    const float* lt     = (const float*)d_in[8];
    float* out = (float*)d_out;

    prep_kernel<<<NF*NK, 256>>>(qw, mu_lat, ls_lat, mu_lon, ls_lon, mu_lev, ls_lev, lt);
    feat_kernel<<<NB*NF, 256>>>(patch, qw, out);
}

// round 2
// speedup vs baseline: 1.4213x; 1.4213x over previous
#include <cuda_runtime.h>
#include <cstdint>

// Problem constants
#define NF 8
#define NK 16
#define NY 16
#define NX 16
#define NP 32
#define NT 8
#define NB 64
#define VOL (NY*NX*NP*NT)   // 65536 elements per (b,f)
#define COLS (NY*NX*NP)     // 8192 (y,x,p) points per (b,f)
#define CHUNKS 4
#define PTS_PER_CHUNK (COLS/CHUNKS)      // 2048 points
#define J_PER_CHUNK (PTS_PER_CHUNK/256)  // 8 iterations
#define YX_PER_CHUNK (PTS_PER_CHUNK/NP)  // 64 yx per chunk

// Small precomputed tables (device globals — no allocation allowed)
__device__ float g_klat[NF*NK*NY];
__device__ float g_klon[NF*NK*NX];
__device__ float g_klev[NF*NK*NP];
__device__ float g_r[NF*NK];      // geometric ratio exp(-1/tau)
__device__ float g_rinv[NF*NK];   // 1 / (integrated + 1e-4)

using u64 = unsigned long long;

// Packed f32x2 helpers (B300 packed fp32 pipe)
__device__ __forceinline__ u64 pk2(float lo, float hi) {
    u64 r; asm("mov.b64 %0,{%1,%2};" : "=l"(r) : "f"(lo), "f"(hi)); return r;
}
__device__ __forceinline__ u64 fma2(u64 a, u64 b, u64 c) {
    u64 d; asm("fma.rn.f32x2 %0,%1,%2,%3;" : "=l"(d) : "l"(a), "l"(b), "l"(c)); return d;
}
__device__ __forceinline__ u64 mul2(u64 a, u64 b) {
    u64 d; asm("mul.rn.f32x2 %0,%1,%2;" : "=l"(d) : "l"(a), "l"(b)); return d;
}
__device__ __forceinline__ float2 up2(u64 a) {
    float2 v; asm("mov.b64 {%0,%1},%2;" : "=f"(v.x), "=f"(v.y) : "l"(a)); return v;
}

// ---------------------------------------------------------------------------
// Prep kernel: one CTA per (f,k). Builds 1D kernel tables, geometric ratio r,
// integrated[f,k] (vectorized float4 qw reads + scalar Horner over t), and
// zeroes the output buffer (feat accumulates into it with atomicAdd).
// ---------------------------------------------------------------------------
__global__ __launch_bounds__(256)
void prep_kernel(const float* __restrict__ qw,
                 const float* __restrict__ mu_lat, const float* __restrict__ ls_lat,
                 const float* __restrict__ mu_lon, const float* __restrict__ ls_lon,
                 const float* __restrict__ mu_lev, const float* __restrict__ ls_lev,
                 const float* __restrict__ lt_time,
                 float* __restrict__ out)
{
    const int fk = blockIdx.x;    // f*NK + k
    const int tid = threadIdx.x;
    __shared__ float s_lat[NY], s_lon[NX], s_lev[NP];
    __shared__ float s_part[8];

    // Zero the output region this CTA owns (8192 floats over 128 CTAs)
    if (tid < 64) out[fk*64 + tid] = 0.f;

    if (tid < NY) {
        float c = -1.f + 2.f * (float)tid / (float)(NY - 1);
        float z = (c - mu_lat[fk]) / expf(ls_lat[fk]);
        float v = expf(-0.5f * z * z);
        s_lat[tid] = v; g_klat[fk*NY + tid] = v;
    } else if (tid < 32) {
        int x = tid - 16;
        float c = -1.f + 2.f * (float)x / (float)(NX - 1);
        float z = (c - mu_lon[fk]) / expf(ls_lon[fk]);
        float v = expf(-0.5f * z * z);
        s_lon[x] = v; g_klon[fk*NX + x] = v;
    } else if (tid < 64) {
        int p = tid - 32;
        float c = -1.f + 2.f * (float)p / (float)(NP - 1);
        float z = (c - mu_lev[fk]) / expf(ls_lev[fk]);
        float v = expf(-0.5f * z * z);
        s_lev[p] = v; g_klev[fk*NP + p] = v;
    }
    // Every thread computes r locally (cheap MUFU); one thread publishes it.
    float tau = expf(lt_time[fk]) + 1e-6f;
    float r = expf(-1.f / tau);
    if (tid == 0) g_r[fk] = r;
    __syncthreads();

    // integrated = sum over 8192 (y,x,p) points: Horner over t, times sep weights
    const float4* q4 = (const float4*)qw;
    float local = 0.f;
    for (int it = 0; it < COLS/256; ++it) {
        int idx = it*256 + tid;       // point index
        float4 q0 = q4[idx*2];
        float4 q1 = q4[idx*2 + 1];
        float s = q1.w;
        s = fmaf(s, r, q1.z); s = fmaf(s, r, q1.y); s = fmaf(s, r, q1.x);
        s = fmaf(s, r, q0.w); s = fmaf(s, r, q0.z); s = fmaf(s, r, q0.y);
        s = fmaf(s, r, q0.x);
        int p = idx & 31, x = (idx >> 5) & 15, y = idx >> 9;
        local += s * (s_lat[y] * s_lon[x] * s_lev[p]);
    }
    #pragma unroll
    for (int o = 16; o; o >>= 1) local += __shfl_xor_sync(0xffffffffu, local, o);
    if ((tid & 31) == 0) s_part[tid >> 5] = local;
    __syncthreads();
    if (tid == 0) {
        float s = 0.f;
        #pragma unroll
        for (int w = 0; w < 8; ++w) s += s_part[w];
        g_rinv[fk] = 1.f / (s + 1e-4f);
    }
}

// ---------------------------------------------------------------------------
// Main kernel: grid = NB*NF*CHUNKS (2048 CTAs, 256 threads).
// CTA (bf, chunk) processes a contiguous quarter of the 8192 (y,x,p) points
// for one (b,f) pair and atomically accumulates scaled partials into out.
// Thread layout: p = tid & 31 constant per thread -> klev applied in epilogue.
// Inner math: packed Horner over t (ktime is geometric) for 8 k-pairs.
// ---------------------------------------------------------------------------
__global__ __launch_bounds__(256, 3)
void feat_kernel(const float* __restrict__ patch,
                 const float* __restrict__ qw,
                 float* __restrict__ out)
{
    const int bid  = blockIdx.x;
    const int bf   = bid & (NB*NF - 1);
    const int chunk = bid >> 9;
    const int f    = bf & (NF - 1);
    const int tid  = threadIdx.x;

    __shared__ __align__(16) float s_cl[YX_PER_CHUNK*NK];   // 4 KB
    __shared__ float s_red[8*NK];

    // Combined lat*lon table for this f, restricted to this chunk's yx range
    for (int i = tid; i < YX_PER_CHUNK*NK; i += 256) {
        int k   = i & 15;
        int yx  = chunk*YX_PER_CHUNK + (i >> 4);
        s_cl[i] = g_klat[(f*NK + k)*NY + (yx >> 4)] * g_klon[(f*NK + k)*NX + (yx & 15)];
    }

    u64 r2[8], acc[8];
    #pragma unroll
    for (int kp = 0; kp < 8; ++kp) {
        int k0 = f*NK + 2*kp;
        r2[kp]  = pk2(g_r[k0], g_r[k0+1]);
        acc[kp] = 0ull;
    }
    __syncthreads();

    const float4* pbase = (const float4*)(patch + (size_t)bf * VOL)
                          + (size_t)chunk * (PTS_PER_CHUNK*2);
    const float4* qbase = (const float4*)qw + (size_t)chunk * (PTS_PER_CHUNK*2);

    #pragma unroll 2
    for (int j = 0; j < J_PER_CHUNK; ++j) {
        const int il = j*256 + tid;       // local point index within chunk
        float4 a0 = pbase[il*2];
        float4 a1 = pbase[il*2 + 1];
        float4 q0 = qbase[il*2];
        float4 q1 = qbase[il*2 + 1];

        float wp0 = a0.x*q0.x, wp1 = a0.y*q0.y, wp2 = a0.z*q0.z, wp3 = a0.w*q0.w;
        float wp4 = a1.x*q1.x, wp5 = a1.y*q1.y, wp6 = a1.z*q1.z, wp7 = a1.w*q1.w;
        u64 w[8];
        w[0] = pk2(wp0, wp0); w[1] = pk2(wp1, wp1);
        w[2] = pk2(wp2, wp2); w[3] = pk2(wp3, wp3);
        w[4] = pk2(wp4, wp4); w[5] = pk2(wp5, wp5);
        w[6] = pk2(wp6, wp6); w[7] = pk2(wp7, wp7);

        const u64* cl = (const u64*)(s_cl + (il >> 5) * NK);  // warp-uniform

        #pragma unroll
        for (int kp = 0; kp < 8; ++kp) {
            u64 s = w[7];
            #pragma unroll
            for (int t = 6; t >= 0; --t) s = fma2(s, r2[kp], w[t]);
            acc[kp] = fma2(s, cl[kp], acc[kp]);
        }
    }

    // Epilogue: apply klev (per-thread constant p), reduce 256 -> 1 per k,
    // scale by 1/integrated, atomically accumulate into out.
    const int p = tid & 31;
    float v[16];
    #pragma unroll
    for (int kp = 0; kp < 8; ++kp) {
        int k0 = f*NK + 2*kp;
        u64 kv2 = pk2(g_klev[k0*NP + p], g_klev[(k0+1)*NP + p]);
        float2 t2 = up2(mul2(acc[kp], kv2));
        v[2*kp]   = t2.x;
        v[2*kp+1] = t2.y;
    }
    #pragma unroll
    for (int kk = 0; kk < 16; ++kk) {
        #pragma unroll
        for (int o = 16; o; o >>= 1) v[kk] += __shfl_xor_sync(0xffffffffu, v[kk], o);
    }
    const int lane = tid & 31, wrp = tid >> 5;
    if (lane == 0) {
        #pragma unroll
        for (int kk = 0; kk < 16; ++kk) s_red[wrp*NK + kk] = v[kk];
    }
    __syncthreads();
    if (tid < NK) {
        float s = 0.f;
        #pragma unroll
        for (int w8 = 0; w8 < 8; ++w8) s += s_red[w8*NK + tid];
        atomicAdd(&out[(size_t)(bf >> 3) * (NF*NK) + f*NK + tid],
                  s * g_rinv[f*NK + tid]);
    }
}

// ---------------------------------------------------------------------------
// Launch. Inputs (metadata order): patch, quadweights, mu_lat, logsigma_lat,
// mu_lon, logsigma_lon, mu_lev, logsigma_lev, logtau_time.
// ---------------------------------------------------------------------------
extern "C" void kernel_launch(void* const* d_in, const int* in_sizes, int n_in,
                              void* d_out, int out_size)
{
    (void)in_sizes; (void)n_in; (void)out_size;
    const float* patch  = (const float*)d_in[0];
    const float* qw     = (const float*)d_in[1];
    const float* mu_lat = (const float*)d_in[2];
    const float* ls_lat = (const float*)d_in[3];
    const float* mu_lon = (const float*)d_in[4];
    const float* ls_lon = (const float*)d_in[5];
    const float* mu_lev = (const float*)d_in[6];
    const float* ls_lev = (const float*)d_in[7];
    const float* lt     = (const float*)d_in[8];
    float* out = (float*)d_out;

    prep_kernel<<<NF*NK, 256>>>(qw, mu_lat, ls_lat, mu_lon, ls_lon,
                                mu_lev, ls_lev, lt, out);
    feat_kernel<<<NB*NF*CHUNKS, 256>>>(patch, qw, out);
}